// round 12
// baseline (speedup 1.0000x reference)
#include <cuda_runtime.h>
#include <cuda_bf16.h>
#include <cstdint>

// ---------------------------------------------------------------- problem
#define NROWS    32768
#define DIM      64
#define KCODES   1024
#define MTILE    128             // rows per CTA
#define NC       128             // codes per chunk (2 halves of 64)
#define NCHUNK   (KCODES / NC)   // 8
#define NCTAS    (NROWS / MTILE) // 256
#define TPB      256             // 8 warps, 16 rows each
#define TAU      5e-5f
#define CAP      8               // per-lane (covers a 512-code subset)

// Output layout (flattened fp32): [quantized_st | vq_loss | indices | perplexity]
#define OFF_Q   0
#define OFF_L   2097152
#define OFF_I   2097153
#define OFF_P   2129921

// ---------------------------------------------------------------- smem layout
#define RSA 144                  // bf16 tile row stride (bytes): conflict-free
#define RSS 272                  // score tile row stride (bytes)

#define BHALF    (NC * RSA)                  // 18432 (hi or lo tile)
#define BBUF     (2 * BHALF)                 // 36864 per buffer
#define SM_B0    0                           // two B buffers: 73728
#define SM_SC    (2 * BBUF)                  // 73728 (+34816)
#define SM_ESQ   (SM_SC + MTILE * RSS)       // 108544 (+4096)
#define SM_TOTAL (SM_ESQ + KCODES * 4)       // 112640 (2 CTAs/SM)

// ---------------------------------------------------------------- scratch
__device__ __align__(16) __nv_bfloat16 g_zhi[NROWS * DIM];
__device__ __align__(16) __nv_bfloat16 g_zlo[NROWS * DIM];
__device__ __align__(16) __nv_bfloat16 g_ehi[KCODES * DIM];
__device__ __align__(16) __nv_bfloat16 g_elo[KCODES * DIM];
__device__ float  g_esq[KCODES];
__device__ int    g_counts[KCODES];
__device__ double g_losssum;

// ---------------------------------------------------------------- PTX helpers
__device__ __forceinline__ uint32_t smem_u32(const void* p) {
    uint32_t a;
    asm("{ .reg .u64 t; cvta.to.shared.u64 t, %1; cvt.u32.u64 %0, t; }"
        : "=r"(a) : "l"(p));
    return a;
}
__device__ __forceinline__ void mma16816(float (&c)[4],
                                         const uint32_t (&a)[4],
                                         uint32_t b0, uint32_t b1) {
    asm("mma.sync.aligned.m16n8k16.row.col.f32.bf16.bf16.f32 "
        "{%0,%1,%2,%3}, {%4,%5,%6,%7}, {%8,%9}, {%0,%1,%2,%3};"
        : "+f"(c[0]), "+f"(c[1]), "+f"(c[2]), "+f"(c[3])
        : "r"(a[0]), "r"(a[1]), "r"(a[2]), "r"(a[3]), "r"(b0), "r"(b1));
}
__device__ __forceinline__ void ldx4(uint32_t* r, uint32_t addr) {
    asm volatile("ldmatrix.sync.aligned.m8n8.x4.shared.b16 {%0,%1,%2,%3}, [%4];"
        : "=r"(r[0]), "=r"(r[1]), "=r"(r[2]), "=r"(r[3]) : "r"(addr));
}
__device__ __forceinline__ void cpasync16(uint32_t dst, const void* src) {
    asm volatile("cp.async.cg.shared.global [%0], [%1], 16;"
                 :: "r"(dst), "l"(src));
}
#define CP_COMMIT() asm volatile("cp.async.commit_group;" ::: "memory")
#define CP_WAIT0()  asm volatile("cp.async.wait_group 0;" ::: "memory")

// ---------------------------------------------------------------- prep kernels
__global__ void vq_prep_z(const float* __restrict__ z, int half) {
    int i = half * (NROWS * DIM / 2) + blockIdx.x * 256 + threadIdx.x;
    float v = z[i];
    __nv_bfloat16 h = __float2bfloat16(v);
    g_zhi[i] = h;
    g_zlo[i] = __float2bfloat16(v - __bfloat162float(h));
}

__global__ void vq_prep_cb(const float* __restrict__ codebook) {
    int i = blockIdx.x * 256 + threadIdx.x;   // 65536 threads
    float v = codebook[i];
    __nv_bfloat16 h = __float2bfloat16(v);
    g_ehi[i] = h;
    g_elo[i] = __float2bfloat16(v - __bfloat162float(h));
    int wcode = i >> 5, lane = i & 31;
    if (wcode < KCODES) {
        const float2* e = reinterpret_cast<const float2*>(codebook + wcode * DIM);
        float2 t = e[lane];
        float s = fmaf(t.x, t.x, t.y * t.y);
        #pragma unroll
        for (int off = 16; off; off >>= 1)
            s += __shfl_xor_sync(0xffffffffu, s, off);
        if (lane == 0) g_esq[wcode] = s;
    }
    if (i < KCODES) g_counts[i] = 0;
    if (i == 0) g_losssum = 0.0;
}

// ---------------------------------------------------------------- main
__global__ __launch_bounds__(TPB, 2) void vq_main(
    const float* __restrict__ z,
    const float* __restrict__ codebook,
    float* __restrict__ out)
{
    extern __shared__ char smem[];
    const uint32_t sb = smem_u32(smem);
    const int tid  = threadIdx.x;
    const int wid  = tid >> 5;
    const int lane = tid & 31;
    const int g    = lane >> 2;     // groupID
    const int tg   = lane & 3;      // threadID in group
    const int row0 = blockIdx.x * MTILE;

    float* sesq = reinterpret_cast<float*>(smem + SM_ESQ);

    // ---- async-stage B chunk 0 -> buf0 and A (z hi/lo) -> buf1; esq normal
    {
        #pragma unroll
        for (int k = 0; k < 4; ++k) {
            int i = tid + k * TPB;                 // 0..1023
            uint32_t dst = sb + SM_B0 + (uint32_t)(i >> 3) * RSA + (i & 7) * 16;
            cpasync16(dst, g_ehi + (size_t)i * 8);
            cpasync16(dst + BHALF, g_elo + (size_t)i * 8);
            uint32_t dsa = sb + SM_B0 + BBUF + (uint32_t)(i >> 3) * RSA + (i & 7) * 16;
            cpasync16(dsa, g_zhi + (size_t)row0 * DIM + (size_t)i * 8);
            cpasync16(dsa + BHALF, g_zlo + (size_t)row0 * DIM + (size_t)i * 8);
        }
        CP_COMMIT();
        #pragma unroll
        for (int i = tid; i < KCODES; i += TPB) sesq[i] = g_esq[i];
    }
    CP_WAIT0();
    __syncthreads();

    // ---- A fragments resident in registers (ldmatrix from buf1 staging)
    uint32_t ahr[4][4], alr[4][4];
    {
        const uint32_t abase = sb + SM_B0 + BBUF
            + (uint32_t)(16 * wid + (lane & 7) + ((lane >> 3) & 1) * 8) * RSA
            + ((lane >> 4) & 1) * 16;
        #pragma unroll
        for (int t = 0; t < 4; ++t) {
            ldx4(ahr[t], abase + 32 * t);
            ldx4(alr[t], abase + BHALF + 32 * t);
        }
    }
    __syncthreads();   // buf1 now free for B chunk 1

    // per-lane candidate state (lane pair shares a row; half = lane&1)
    const int lrow = 16 * wid + (lane >> 1);
    const int half = lane & 1;
    float smin = 3.402823466e38f;
    int   ncand = 0;
    bool  ovf = false;
    int   ck[CAP];
    float cs[CAP];

#define TRY_INSERT(kk, ss) do {                                               \
    if ((ss) <= smin + TAU) {                                                 \
        if (ncand < CAP) { ck[ncand] = (kk); cs[ncand] = (ss); ++ncand; }     \
        else {                                                                 \
            int m_ = 0;                                                        \
            for (int ii = 0; ii < CAP; ++ii)                                   \
                if (cs[ii] <= smin + TAU) { ck[m_] = ck[ii]; cs[m_] = cs[ii]; ++m_; } \
            ncand = m_;                                                        \
            if (ncand < CAP) { ck[ncand] = (kk); cs[ncand] = (ss); ++ncand; }  \
            else ovf = true;                                                   \
        }                                                                      \
    } } while (0)

    // per-lane B fragment address component
    const uint32_t bbase = (uint32_t)((lane & 7) + ((lane >> 4) & 1) * 8) * RSA
                         + ((lane >> 3) & 1) * 16;

    for (int c = 0; c < NCHUNK; ++c) {
        // ---- async prefetch chunk c+1 into the other buffer
        if (c + 1 < NCHUNK) {
            uint32_t bd = sb + SM_B0 + ((c + 1) & 1) * BBUF;
            const __nv_bfloat16* sh = g_ehi + (size_t)(c + 1) * NC * DIM;
            const __nv_bfloat16* sl = g_elo + (size_t)(c + 1) * NC * DIM;
            #pragma unroll
            for (int k = 0; k < 4; ++k) {
                int i = tid + k * TPB;
                uint32_t dst = bd + (uint32_t)(i >> 3) * RSA + (i & 7) * 16;
                cpasync16(dst, sh + (size_t)i * 8);
                cpasync16(dst + BHALF, sl + (size_t)i * 8);
            }
            CP_COMMIT();
        }

        const uint32_t BT = sb + SM_B0 + (c & 1) * BBUF;

        #pragma unroll
        for (int h = 0; h < 2; ++h) {           // 64-code halves
            const uint32_t hb = BT + h * (64 * RSA) + bbase;

            float acc[8][4];
            #pragma unroll
            for (int j = 0; j < 8; ++j)
                #pragma unroll
                for (int q = 0; q < 4; ++q) acc[j][q] = 0.f;

            #pragma unroll
            for (int t = 0; t < 4; ++t) {
                #pragma unroll
                for (int jb = 0; jb < 2; ++jb) {     // 4 n-tiles per group
                    uint32_t bh[8], bl[8];
                    uint32_t p0 = hb + (2 * jb) * (16 * RSA) + 32 * t;
                    uint32_t p1 = hb + (2 * jb + 1) * (16 * RSA) + 32 * t;
                    ldx4(&bh[0], p0);
                    ldx4(&bh[4], p1);
                    ldx4(&bl[0], p0 + BHALF);
                    ldx4(&bl[4], p1 + BHALF);
                    // pass-major: dependent MMAs on same acc are 4 apart
                    #pragma unroll
                    for (int jj = 0; jj < 4; ++jj)
                        mma16816(acc[4 * jb + jj], ahr[t], bh[2 * jj], bh[2 * jj + 1]);
                    #pragma unroll
                    for (int jj = 0; jj < 4; ++jj)
                        mma16816(acc[4 * jb + jj], alr[t], bh[2 * jj], bh[2 * jj + 1]);
                    #pragma unroll
                    for (int jj = 0; jj < 4; ++jj)
                        mma16816(acc[4 * jb + jj], ahr[t], bl[2 * jj], bl[2 * jj + 1]);
                }
            }

            // ---- transpose with esq fused: write final scores s = esq - 2m
            const int kb = c * NC + h * 64;
            #pragma unroll
            for (int j = 0; j < 8; ++j) {
                float2 eq = *reinterpret_cast<const float2*>(sesq + kb + 8 * j + 2 * tg);
                float s0 = __fmaf_rn(-2.f, acc[j][0], eq.x);
                float s1 = __fmaf_rn(-2.f, acc[j][1], eq.y);
                float s2 = __fmaf_rn(-2.f, acc[j][2], eq.x);
                float s3 = __fmaf_rn(-2.f, acc[j][3], eq.y);
                uint32_t r0 = (uint32_t)(16 * wid + g);
                uint32_t coff = (uint32_t)(8 * j + 2 * tg) * 4;
                *reinterpret_cast<float2*>(smem + SM_SC + r0 * RSS + coff) = make_float2(s0, s1);
                *reinterpret_cast<float2*>(smem + SM_SC + (r0 + 8) * RSS + coff) = make_float2(s2, s3);
            }
            __syncwarp();

            // ---- single-pass scan of own 32 codes (insert, then update smin)
            {
                const float4* srow = reinterpret_cast<const float4*>(
                    smem + SM_SC + (uint32_t)lrow * RSS + half * 128);
                int k0 = kb + half * 32;
                #pragma unroll
                for (int q = 0; q < 8; ++q) {
                    float4 s4 = srow[q];
                    TRY_INSERT(k0 + 4 * q + 0, s4.x); smin = fminf(smin, s4.x);
                    TRY_INSERT(k0 + 4 * q + 1, s4.y); smin = fminf(smin, s4.y);
                    TRY_INSERT(k0 + 4 * q + 2, s4.z); smin = fminf(smin, s4.z);
                    TRY_INSERT(k0 + 4 * q + 3, s4.w); smin = fminf(smin, s4.w);
                }
            }
            __syncwarp();   // all lanes done reading SC before next half overwrites
        }

        if (c + 1 < NCHUNK) CP_WAIT0();
        __syncthreads();
    }

    // ---------------- exact refinement (reference fp32 rounding, R1/R2-proven)
    const int r = row0 + lrow;
    float zq[DIM];
    {
        const float4* zr = reinterpret_cast<const float4*>(z + (size_t)r * DIM);
        #pragma unroll
        for (int i = 0; i < DIM / 4; ++i) {
            float4 t = zr[i];
            zq[4 * i] = t.x; zq[4 * i + 1] = t.y; zq[4 * i + 2] = t.z; zq[4 * i + 3] = t.w;
        }
    }
    float zsq = 0.f;
    #pragma unroll
    for (int i = 0; i < DIM; ++i) zsq = fmaf(zq[i], zq[i], zsq);

    float best = 3.402823466e38f;
    int   bestk = KCODES;
    if (!ovf) {
        for (int i = 0; i < ncand; ++i) {
            if (cs[i] > smin + TAU) continue;
            int k = ck[i];
            const float* e = codebook + (size_t)k * DIM;
            float m = 0.f;
            #pragma unroll
            for (int d = 0; d < DIM; ++d) m = fmaf(zq[d], e[d], m);
            float dd = __fmaf_rn(-2.f, m, zsq + sesq[k]);
            if (dd < best || (dd == best && k < bestk)) { best = dd; bestk = k; }
        }
    } else {
        // exact scan over this lane's own 512-code subset (32 per 64-block)
        for (int blk = 0; blk < KCODES / 64; ++blk) {
            int kb = blk * 64 + half * 32;
            for (int kk = 0; kk < 32; ++kk) {
                int k = kb + kk;
                const float* e = codebook + (size_t)k * DIM;
                float m = 0.f;
                #pragma unroll
                for (int d = 0; d < DIM; ++d) m = fmaf(zq[d], e[d], m);
                float dd = __fmaf_rn(-2.f, m, zsq + sesq[k]);
                if (dd < best || (dd == best && k < bestk)) { best = dd; bestk = k; }
            }
        }
    }

    // merge lane pair: smaller exact d, tie -> smaller k (jnp first-min rule)
    {
        float ob = __shfl_xor_sync(0xffffffffu, best, 1);
        int   ok = __shfl_xor_sync(0xffffffffu, bestk, 1);
        if (ob < best || (ob == best && ok < bestk)) { best = ob; bestk = ok; }
    }

    // ---------------- outputs: stage quantized row halves into SC, loss partials
    float lsum = 0.f;
    {
        const float* eb = codebook + (size_t)bestk * DIM + half * 32;
        const float* zh = zq + half * 32;
        float* qrow = reinterpret_cast<float*>(smem + SM_SC + (uint32_t)lrow * RSS) + half * 32;
        #pragma unroll
        for (int i = 0; i < 8; ++i) {
            float d0 = eb[4 * i + 0] - zh[4 * i + 0];
            float d1 = eb[4 * i + 1] - zh[4 * i + 1];
            float d2 = eb[4 * i + 2] - zh[4 * i + 2];
            float d3 = eb[4 * i + 3] - zh[4 * i + 3];
            float4 qv = make_float4(zh[4 * i + 0] + d0, zh[4 * i + 1] + d1,
                                    zh[4 * i + 2] + d2, zh[4 * i + 3] + d3);
            *reinterpret_cast<float4*>(qrow + 4 * i) = qv;
            lsum = fmaf(d0, d0, lsum); lsum = fmaf(d1, d1, lsum);
            lsum = fmaf(d2, d2, lsum); lsum = fmaf(d3, d3, lsum);
        }
        if (half == 0) {
            out[OFF_I + r] = (float)bestk;
            atomicAdd(&g_counts[bestk], 1);   // spread-address REDG
        }
    }
    #pragma unroll
    for (int off = 16; off; off >>= 1)
        lsum += __shfl_down_sync(0xffffffffu, lsum, off);
    if (lane == 0) atomicAdd(&g_losssum, (double)lsum);

    // coalesced copy of quantized tile SC -> gmem
    __syncthreads();
    float* oq = out + OFF_Q + (size_t)row0 * DIM;
    #pragma unroll
    for (int i = tid; i < MTILE * (DIM / 4); i += TPB) {
        int rw = i >> 4, q = i & 15;
        float4 v = *reinterpret_cast<const float4*>(smem + SM_SC + (uint32_t)rw * RSS + q * 16);
        reinterpret_cast<float4*>(oq + (size_t)rw * DIM)[q] = v;
    }
}

// ---------------------------------------------------------------- finalize
__global__ void vq_final(float* __restrict__ out) {
    __shared__ double red[32];
    int t = threadIdx.x;  // 1024 threads
    float c = (float)g_counts[t];
    float p = c * (1.0f / 32768.0f);
    float term = p * logf(p + 1e-10f);
    double v = (double)term;
    #pragma unroll
    for (int off = 16; off; off >>= 1)
        v += __shfl_down_sync(0xffffffffu, v, off);
    if ((t & 31) == 0) red[t >> 5] = v;
    __syncthreads();
    if (t < 32) {
        double w = red[t];
        #pragma unroll
        for (int off = 16; off; off >>= 1)
            w += __shfl_down_sync(0xffffffffu, w, off);
        if (t == 0) {
            float s = (float)w;
            out[OFF_P] = expf(-s);
            float m = (float)(g_losssum * (1.0 / 2097152.0));
            out[OFF_L] = m + 0.25f * m;
        }
    }
}

// ---------------------------------------------------------------- launch
extern "C" void kernel_launch(void* const* d_in, const int* in_sizes, int n_in,
                              void* d_out, int out_size) {
    const float* z        = (const float*)d_in[0];
    const float* codebook = (const float*)d_in[1];
    float* out = (float*)d_out;

    cudaFuncSetAttribute(vq_main, cudaFuncAttributeMaxDynamicSharedMemorySize, SM_TOTAL);

    vq_prep_z<<<4096, 256>>>(z, 0);                       // idx 0
    vq_prep_z<<<4096, 256>>>(z, 1);                       // idx 1
    vq_prep_cb<<<256, 256>>>(codebook);                   // idx 2
    vq_main<<<NCTAS, TPB, SM_TOTAL>>>(z, codebook, out);  // idx 3 (ncu slot)
    vq_final<<<1, KCODES>>>(out);                         // idx 4
}